// round 6
// baseline (speedup 1.0000x reference)
#include <cuda_runtime.h>

#define TPB 128
typedef unsigned long long ull;

// ---- flat constant layout (floats duplicated to {w,w} 64-bit pairs) ----
#define OFF_mW0 0
#define OFF_mb0 16
#define OFF_mW1 24
#define OFF_mb1 88
#define OFF_mW2 96
#define OFF_mb2 128
#define OFF_pW1 132
#define OFF_pb1 164
#define OFF_pW2 180
#define OFF_pb2 308
#define OFF_pW3 324
#define OFF_pb3 340
#define NPARAM 342

__constant__ ull cW[NPARAM];
__device__ ull g_stage[NPARAM];

__global__ void pack_kernel(const float* mW0, const float* mb0, const float* mW1,
                            const float* mb1, const float* mW2, const float* mb2,
                            const float* pW1, const float* pb1, const float* pW2,
                            const float* pb2, const float* pW3, const float* pb3)
{
    const float* srcs[12] = {mW0, mb0, mW1, mb1, mW2, mb2,
                             pW1, pb1, pW2, pb2, pW3, pb3};
    const int lens[12] = {16, 8, 64, 8, 32, 4, 32, 16, 128, 16, 16, 2};
    int off = 0;
    for (int k = 0; k < 12; k++) {
        for (int i = threadIdx.x; i < lens[k]; i += blockDim.x) {
            unsigned u = __float_as_uint(srcs[k][i]);
            g_stage[off + i] = (ull)u | ((ull)u << 32);
        }
        off += lens[k];
    }
}

// ---- packed f32x2 primitives ----
__device__ __forceinline__ ull f2pk(float lo, float hi) {
    ull r; asm("mov.b64 %0,{%1,%2};" : "=l"(r) : "f"(lo), "f"(hi)); return r;
}
__device__ __forceinline__ void f2up(ull v, float& lo, float& hi) {
    asm("mov.b64 {%0,%1},%2;" : "=f"(lo), "=f"(hi) : "l"(v));
}
__device__ __forceinline__ ull ffma2(ull a, ull b, ull c) {
    ull d; asm("fma.rn.f32x2 %0,%1,%2,%3;" : "=l"(d) : "l"(a), "l"(b), "l"(c)); return d;
}
__device__ __forceinline__ ull fmul2(ull a, ull b) {
    ull d; asm("mul.rn.f32x2 %0,%1,%2;" : "=l"(d) : "l"(a), "l"(b)); return d;
}

#define C_MONE  0xBF800000BF800000ULL   // {-1,-1}
#define C_HALF  0x3F0000003F000000ULL   // {0.5,0.5}

__device__ __forceinline__ float ex2_apx(float x) {
    float y; asm("ex2.approx.f32 %0, %1;" : "=f"(y) : "f"(x)); return y;
}
__device__ __forceinline__ float tanh_apx(float x) {
    float y; asm("tanh.approx.f32 %0, %1;" : "=f"(y) : "f"(x)); return y;
}
__device__ __forceinline__ ull tanh2(ull z) {
    float lo, hi; f2up(z, lo, hi);
    return f2pk(tanh_apx(lo), tanh_apx(hi));
}
__device__ __forceinline__ float sigm_f(float x) {
    return fmaf(0.5f, tanh_apx(0.5f * x), 0.5f);
}
__device__ __forceinline__ ull elu2(ull z) {
    const float L2E = 1.4426950408889634f;
    float lo, hi; f2up(z, lo, hi);
    float elo = ex2_apx(lo * L2E) - 1.0f;
    float ehi = ex2_apx(hi * L2E) - 1.0f;
    lo = lo > 0.0f ? lo : elo;
    hi = hi > 0.0f ? hi : ehi;
    return f2pk(lo, hi);
}
// d = s*(1-s), s = sigmoid(sigmoid(z))  (reference applies sigmoid twice)
__device__ __forceinline__ float dsig(float z) {
    float s = sigm_f(sigm_f(z));
    return fmaf(-s, s, s);
}

__global__ void __launch_bounds__(TPB, 5)
ode_kernel(const float* __restrict__ x, float* __restrict__ out, int npairs)
{
    int t = blockIdx.x * TPB + threadIdx.x;
    if (t >= npairs) return;

    float4 xv = ((const float4*)x)[t];
    ull X0 = f2pk(xv.x, xv.z);   // lo = point a, hi = point b
    ull X1 = f2pk(xv.y, xv.w);

    // ---------- p-net ensemble: forward + fused backward accumulation ----------
    // Backward restructure: d (sigmoid deriv) factors out of the whole chain, so
    // accumulate accp[p] = sum_q W3[q]*(f2_q^2-1)*W2[q][p] inside the forward
    // q-loop; f2_q is consumed immediately (no f2v[]/gq[] arrays -> lower regs).
    ull gi0 = 0ULL, gi1 = 0ULL;
#pragma unroll
    for (int v = 0; v < 2; v++) {
        ull f1[8];
#pragma unroll
        for (int p = 0; p < 8; p++) {
            ull z = ffma2(cW[OFF_pW1 + v*16 + 2*p], X0,
                     ffma2(cW[OFF_pW1 + v*16 + 2*p + 1], X1, cW[OFF_pb1 + v*8 + p]));
            f1[p] = tanh2(z);
        }

        ull accp[8];
#pragma unroll
        for (int p = 0; p < 8; p++) accp[p] = 0ULL;
        ull z3 = cW[OFF_pb3 + v];

#pragma unroll
        for (int q = 0; q < 8; q++) {
            ull z = cW[OFF_pb2 + v*8 + q];
#pragma unroll
            for (int p = 0; p < 8; p++)
                z = ffma2(cW[OFF_pW2 + v*64 + q*8 + p], f1[p], z);
            ull f2 = tanh2(z);
            ull w3q = cW[OFF_pW3 + v*8 + q];
            z3 = ffma2(w3q, f2, z3);
            ull tq = fmul2(w3q, ffma2(f2, f2, C_MONE));   // W3q*(f2^2-1)
#pragma unroll
            for (int p = 0; p < 8; p++)
                accp[p] = ffma2(tq, cW[OFF_pW2 + v*64 + q*8 + p], accp[p]);
        }

        float zlo, zhi; f2up(z3, zlo, zhi);
        ull d2 = f2pk(dsig(zlo), dsig(zhi));

#pragma unroll
        for (int p = 0; p < 8; p++) {
            ull a = fmul2(fmul2(d2, accp[p]),
                          ffma2(f1[p], f1[p], C_MONE));   // signs cancel
            gi0 = ffma2(a, cW[OFF_pW1 + v*16 + 2*p], gi0);
            gi1 = ffma2(a, cW[OFF_pW1 + v*16 + 2*p + 1], gi1);
        }
    }
    ull g0 = fmul2(gi0, C_HALF);   // mean over NV=2
    ull g1 = fmul2(gi1, C_HALF);

    // ---------- m-net: 2 -> 8 -> 8 -> 4 (ELU); only g0/g1 live across ----------
    ull h[8];
#pragma unroll
    for (int o = 0; o < 8; o++) {
        ull z = ffma2(cW[OFF_mW0 + 2*o], X0,
                 ffma2(cW[OFF_mW0 + 2*o + 1], X1, cW[OFF_mb0 + o]));
        h[o] = elu2(z);
    }
    ull h2[8];
#pragma unroll
    for (int q = 0; q < 8; q++) {
        ull z = cW[OFF_mb1 + q];
#pragma unroll
        for (int o = 0; o < 8; o++) z = ffma2(cW[OFF_mW1 + q*8 + o], h[o], z);
        h2[q] = elu2(z);
    }
    ull bm[4];
#pragma unroll
    for (int j = 0; j < 4; j++) {
        ull z = cW[OFF_mb2 + j];
#pragma unroll
        for (int o = 0; o < 8; o++) z = ffma2(cW[OFF_mW2 + j*8 + o], h2[o], z);
        bm[j] = z;
    }
    ull m2    = ffma2(bm[0], bm[1], fmul2(bm[2], bm[3]));
    ull mag00 = ffma2(bm[0], bm[0], fmul2(bm[2], bm[2]));
    ull mag11 = ffma2(bm[1], bm[1], fmul2(bm[3], bm[3]));

    ull O0 = ffma2(mag00, g0, fmul2(m2, g1));
    ull O1 = ffma2(m2, g0, fmul2(mag11, g1));

    float oa, ob, oc, od;
    f2up(O0, oa, ob);
    f2up(O1, oc, od);
    ((float4*)out)[t] = make_float4(oa, oc, ob, od);
}

extern "C" void kernel_launch(void* const* d_in, const int* in_sizes, int n_in,
                              void* d_out, int out_size)
{
    // Input order: t, x, mW0, mb0, mW1, mb1, mW2, mb2, pW1, pb1, pW2, pb2, pW3, pb3
    const float* x = (const float*)d_in[1];
    float* out = (float*)d_out;
    int B = in_sizes[1] / 2;

    pack_kernel<<<1, 128>>>((const float*)d_in[2],  (const float*)d_in[3],
                            (const float*)d_in[4],  (const float*)d_in[5],
                            (const float*)d_in[6],  (const float*)d_in[7],
                            (const float*)d_in[8],  (const float*)d_in[9],
                            (const float*)d_in[10], (const float*)d_in[11],
                            (const float*)d_in[12], (const float*)d_in[13]);

    void* stage_addr = nullptr;
    cudaGetSymbolAddress(&stage_addr, g_stage);
    cudaMemcpyToSymbolAsync(cW, stage_addr, sizeof(ull) * NPARAM, 0,
                            cudaMemcpyDeviceToDevice, (cudaStream_t)0);

    int npairs = B / 2;
    int grid = (npairs + TPB - 1) / TPB;
    ode_kernel<<<grid, TPB>>>(x, out, npairs);
}

// round 8
// speedup vs baseline: 1.5138x; 1.5138x over previous
#include <cuda_runtime.h>

#define TPB 256
typedef unsigned long long ull;

// ---- flat constant layout (floats duplicated to {w,w} 64-bit pairs) ----
#define OFF_mW0 0
#define OFF_mb0 16
#define OFF_mW1 24
#define OFF_mb1 88
#define OFF_mW2 96
#define OFF_mb2 128
#define OFF_pW1 132
#define OFF_pb1 164
#define OFF_pW2 180
#define OFF_pb2 308
#define OFF_pW3 324
#define OFF_pb3 340
#define NPARAM 342

__constant__ ull cW[NPARAM];
__device__ ull g_stage[NPARAM];

__global__ void pack_kernel(const float* mW0, const float* mb0, const float* mW1,
                            const float* mb1, const float* mW2, const float* mb2,
                            const float* pW1, const float* pb1, const float* pW2,
                            const float* pb2, const float* pW3, const float* pb3)
{
    const float* srcs[12] = {mW0, mb0, mW1, mb1, mW2, mb2,
                             pW1, pb1, pW2, pb2, pW3, pb3};
    const int lens[12] = {16, 8, 64, 8, 32, 4, 32, 16, 128, 16, 16, 2};
    int off = 0;
    for (int k = 0; k < 12; k++) {
        for (int i = threadIdx.x; i < lens[k]; i += blockDim.x) {
            unsigned u = __float_as_uint(srcs[k][i]);
            g_stage[off + i] = (ull)u | ((ull)u << 32);
        }
        off += lens[k];
    }
}

// ---- packed f32x2 primitives ----
__device__ __forceinline__ ull f2pk(float lo, float hi) {
    ull r; asm("mov.b64 %0,{%1,%2};" : "=l"(r) : "f"(lo), "f"(hi)); return r;
}
__device__ __forceinline__ void f2up(ull v, float& lo, float& hi) {
    asm("mov.b64 {%0,%1},%2;" : "=f"(lo), "=f"(hi) : "l"(v));
}
__device__ __forceinline__ ull ffma2(ull a, ull b, ull c) {
    ull d; asm("fma.rn.f32x2 %0,%1,%2,%3;" : "=l"(d) : "l"(a), "l"(b), "l"(c)); return d;
}
__device__ __forceinline__ ull fmul2(ull a, ull b) {
    ull d; asm("mul.rn.f32x2 %0,%1,%2;" : "=l"(d) : "l"(a), "l"(b)); return d;
}

#define C_MONE  0xBF800000BF800000ULL   // {-1,-1}
#define C_HALF  0x3F0000003F000000ULL   // {0.5,0.5}

__device__ __forceinline__ float ex2_apx(float x) {
    float y; asm("ex2.approx.f32 %0, %1;" : "=f"(y) : "f"(x)); return y;
}
__device__ __forceinline__ float tanh_apx(float x) {
    float y; asm("tanh.approx.f32 %0, %1;" : "=f"(y) : "f"(x)); return y;
}
__device__ __forceinline__ ull tanh2(ull z) {
    float lo, hi; f2up(z, lo, hi);
    return f2pk(tanh_apx(lo), tanh_apx(hi));
}
__device__ __forceinline__ float sigm_f(float x) {
    return fmaf(0.5f, tanh_apx(0.5f * x), 0.5f);
}
__device__ __forceinline__ ull elu2(ull z) {
    const float L2E = 1.4426950408889634f;
    float lo, hi; f2up(z, lo, hi);
    float elo = ex2_apx(lo * L2E) - 1.0f;
    float ehi = ex2_apx(hi * L2E) - 1.0f;
    lo = lo > 0.0f ? lo : elo;
    hi = hi > 0.0f ? hi : ehi;
    return f2pk(lo, hi);
}
// d = s*(1-s), s = sigmoid(sigmoid(z))  (reference applies sigmoid twice)
__device__ __forceinline__ float dsig(float z) {
    float s = sigm_f(sigm_f(z));
    return fmaf(-s, s, s);
}

__global__ void __launch_bounds__(TPB, 2)
ode_kernel(const float* __restrict__ x, float* __restrict__ out, int npairs)
{
    int t = blockIdx.x * TPB + threadIdx.x;
    if (t >= npairs) return;

    float4 xv = ((const float4*)x)[t];
    ull X0 = f2pk(xv.x, xv.z);   // lo = point a, hi = point b
    ull X1 = f2pk(xv.y, xv.w);

    // ---------- p-net ensemble: forward + fused backward accumulation ----------
    // accp[p] = sum_q W3[q]*(f2_q^2-1)*W2[q][p], built inside the forward q-loop
    // so each f2_q is consumed immediately and each W2[q][p] LDCU feeds two FFMA2s.
    ull gi0 = 0ULL, gi1 = 0ULL;
#pragma unroll
    for (int v = 0; v < 2; v++) {
        ull f1[8];
#pragma unroll
        for (int p = 0; p < 8; p++) {
            ull z = ffma2(cW[OFF_pW1 + v*16 + 2*p], X0,
                     ffma2(cW[OFF_pW1 + v*16 + 2*p + 1], X1, cW[OFF_pb1 + v*8 + p]));
            f1[p] = tanh2(z);
        }

        ull accp[8];
#pragma unroll
        for (int p = 0; p < 8; p++) accp[p] = 0ULL;
        ull z3 = cW[OFF_pb3 + v];

#pragma unroll
        for (int q = 0; q < 8; q++) {
            ull z = cW[OFF_pb2 + v*8 + q];
#pragma unroll
            for (int p = 0; p < 8; p++)
                z = ffma2(cW[OFF_pW2 + v*64 + q*8 + p], f1[p], z);
            ull f2 = tanh2(z);
            ull w3q = cW[OFF_pW3 + v*8 + q];
            z3 = ffma2(w3q, f2, z3);
            ull tq = fmul2(w3q, ffma2(f2, f2, C_MONE));   // W3q*(f2^2-1)
#pragma unroll
            for (int p = 0; p < 8; p++)
                accp[p] = ffma2(tq, cW[OFF_pW2 + v*64 + q*8 + p], accp[p]);
        }

        float zlo, zhi; f2up(z3, zlo, zhi);
        ull d2 = f2pk(dsig(zlo), dsig(zhi));

#pragma unroll
        for (int p = 0; p < 8; p++) {
            ull a = fmul2(fmul2(d2, accp[p]),
                          ffma2(f1[p], f1[p], C_MONE));   // signs cancel
            gi0 = ffma2(a, cW[OFF_pW1 + v*16 + 2*p], gi0);
            gi1 = ffma2(a, cW[OFF_pW1 + v*16 + 2*p + 1], gi1);
        }
    }
    ull g0 = fmul2(gi0, C_HALF);   // mean over NV=2
    ull g1 = fmul2(gi1, C_HALF);

    // ---------- m-net: 2 -> 8 -> 8 -> 4 (ELU); only g0/g1 live across ----------
    ull h[8];
#pragma unroll
    for (int o = 0; o < 8; o++) {
        ull z = ffma2(cW[OFF_mW0 + 2*o], X0,
                 ffma2(cW[OFF_mW0 + 2*o + 1], X1, cW[OFF_mb0 + o]));
        h[o] = elu2(z);
    }
    ull h2[8];
#pragma unroll
    for (int q = 0; q < 8; q++) {
        ull z = cW[OFF_mb1 + q];
#pragma unroll
        for (int o = 0; o < 8; o++) z = ffma2(cW[OFF_mW1 + q*8 + o], h[o], z);
        h2[q] = elu2(z);
    }
    ull bm[4];
#pragma unroll
    for (int j = 0; j < 4; j++) {
        ull z = cW[OFF_mb2 + j];
#pragma unroll
        for (int o = 0; o < 8; o++) z = ffma2(cW[OFF_mW2 + j*8 + o], h2[o], z);
        bm[j] = z;
    }
    ull m2    = ffma2(bm[0], bm[1], fmul2(bm[2], bm[3]));
    ull mag00 = ffma2(bm[0], bm[0], fmul2(bm[2], bm[2]));
    ull mag11 = ffma2(bm[1], bm[1], fmul2(bm[3], bm[3]));

    ull O0 = ffma2(mag00, g0, fmul2(m2, g1));
    ull O1 = ffma2(m2, g0, fmul2(mag11, g1));

    float oa, ob, oc, od;
    f2up(O0, oa, ob);
    f2up(O1, oc, od);
    ((float4*)out)[t] = make_float4(oa, oc, ob, od);
}

extern "C" void kernel_launch(void* const* d_in, const int* in_sizes, int n_in,
                              void* d_out, int out_size)
{
    // Input order: t, x, mW0, mb0, mW1, mb1, mW2, mb2, pW1, pb1, pW2, pb2, pW3, pb3
    const float* x = (const float*)d_in[1];
    float* out = (float*)d_out;
    int B = in_sizes[1] / 2;

    pack_kernel<<<1, 128>>>((const float*)d_in[2],  (const float*)d_in[3],
                            (const float*)d_in[4],  (const float*)d_in[5],
                            (const float*)d_in[6],  (const float*)d_in[7],
                            (const float*)d_in[8],  (const float*)d_in[9],
                            (const float*)d_in[10], (const float*)d_in[11],
                            (const float*)d_in[12], (const float*)d_in[13]);

    void* stage_addr = nullptr;
    cudaGetSymbolAddress(&stage_addr, g_stage);
    cudaMemcpyToSymbolAsync(cW, stage_addr, sizeof(ull) * NPARAM, 0,
                            cudaMemcpyDeviceToDevice, (cudaStream_t)0);

    int npairs = B / 2;
    int grid = (npairs + TPB - 1) / TPB;
    ode_kernel<<<grid, TPB>>>(x, out, npairs);
}